// round 5
// baseline (speedup 1.0000x reference)
#include <cuda_runtime.h>
#include <cuda_bf16.h>
#include <cfloat>
#include <cstdint>

#define BB 32768
#define AA 16
#define HH 256
#define DD 128
#define KK 2048

// ---------------------------------------------------------------------------
// Scratch: bf16 weights/codebook (activations never leave smem).
// ---------------------------------------------------------------------------
__device__ __nv_bfloat16 g_We1b[HH * 64];    // [256][64], k>=16 zero (zero-init)
__device__ __nv_bfloat16 g_We2b[HH * HH];
__device__ __nv_bfloat16 g_We3b[DD * HH];
__device__ __nv_bfloat16 g_Wd1b[HH * DD];
__device__ __nv_bfloat16 g_Wd2b[HH * HH];
__device__ __nv_bfloat16 g_Whb[AA * HH];
__device__ __nv_bfloat16 g_Eb[KK * DD];
__device__ float    g_esq[KK];
__device__ double   g_sums[2];
__device__ unsigned g_ticket;

// smem regions (dynamic, 224KB)
#define R1_OFF 0        // 64KB: sH1 | (esq/red/bestidx) | sD1
#define R2_OFF 65536    // 64KB: sH2 | sQ | sD2
#define R3_OFF 131072   // 64KB: W double-buffer | E double-buffer | sWh
#define R4_OFF 196608   // 32KB: sActB | sEnc
#define SMEM_TOTAL 229376

// ---------------------------------------------------------------------------
// Helpers
// ---------------------------------------------------------------------------
__device__ __forceinline__ unsigned su(const void* p) {
    return (unsigned)__cvta_generic_to_shared(p);
}
__device__ __forceinline__ void cp16(unsigned dst, const void* src) {
    asm volatile("cp.async.cg.shared.global [%0], [%1], 16;\n" :: "r"(dst), "l"(src));
}
__device__ __forceinline__ void cpcommit() { asm volatile("cp.async.commit_group;\n"); }
template <int N>
__device__ __forceinline__ void cpwait() { asm volatile("cp.async.wait_group %0;\n" :: "n"(N)); }

__device__ __forceinline__ void ldm4(unsigned addr, unsigned& r0, unsigned& r1,
                                     unsigned& r2, unsigned& r3) {
    asm volatile("ldmatrix.sync.aligned.m8n8.x4.shared.b16 {%0,%1,%2,%3}, [%4];\n"
                 : "=r"(r0), "=r"(r1), "=r"(r2), "=r"(r3) : "r"(addr));
}
__device__ __forceinline__ void mma_bf16(float* c, unsigned a0, unsigned a1, unsigned a2,
                                         unsigned a3, unsigned b0, unsigned b1) {
    asm volatile(
        "mma.sync.aligned.m16n8k16.row.col.f32.bf16.bf16.f32 "
        "{%0,%1,%2,%3}, {%4,%5,%6,%7}, {%8,%9}, {%0,%1,%2,%3};\n"
        : "+f"(c[0]), "+f"(c[1]), "+f"(c[2]), "+f"(c[3])
        : "r"(a0), "r"(a1), "r"(a2), "r"(a3), "r"(b0), "r"(b1));
}
__device__ __forceinline__ unsigned pack_bf16(float a, float b) {
    __nv_bfloat162 h = __floats2bfloat162_rn(a, b);
    return *reinterpret_cast<unsigned*>(&h);
}

__device__ __forceinline__ void block_reduce_add_to(float v, double* target) {
    __shared__ float sbuf[32];
    int lane = threadIdx.x & 31;
    int wid  = threadIdx.x >> 5;
#pragma unroll
    for (int o = 16; o; o >>= 1) v += __shfl_xor_sync(0xffffffffu, v, o);
    if (lane == 0) sbuf[wid] = v;
    __syncthreads();
    if (wid == 0) {
        int nw = blockDim.x >> 5;
        v = (lane < nw) ? sbuf[lane] : 0.0f;
#pragma unroll
        for (int o = 16; o; o >>= 1) v += __shfl_xor_sync(0xffffffffu, v, o);
        if (lane == 0) atomicAdd(target, (double)v);
    }
}

// ---------------------------------------------------------------------------
// Convert weights+codebook fp32->bf16, compute esq, zero sums/ticket.
// Blocks 0..455: conversion (116736 float4). Blocks 456..463: esq rows.
// ---------------------------------------------------------------------------
__global__ void prep_kernel(const float4* __restrict__ We1, const float4* __restrict__ We2,
                            const float4* __restrict__ We3, const float4* __restrict__ Wd1,
                            const float4* __restrict__ Wd2, const float4* __restrict__ Wh,
                            const float4* __restrict__ E, const float* __restrict__ Ef) {
    int blk = blockIdx.x;
    if (blk < 456) {
        int i = blk * 256 + threadIdx.x;
        const float4* src; uint2* dst; int j, dj;
        if (i < 16384)       { src = We2; dst = (uint2*)g_We2b; j = i;          dj = j; }
        else if (i < 24576)  { src = We3; dst = (uint2*)g_We3b; j = i - 16384;  dj = j; }
        else if (i < 32768)  { src = Wd1; dst = (uint2*)g_Wd1b; j = i - 24576;  dj = j; }
        else if (i < 49152)  { src = Wd2; dst = (uint2*)g_Wd2b; j = i - 32768;  dj = j; }
        else if (i < 114688) { src = E;   dst = (uint2*)g_Eb;   j = i - 49152;  dj = j; }
        else if (i < 115712) { src = We1; dst = (uint2*)g_We1b; j = i - 114688;
                               dj = (j >> 2) * 16 + (j & 3); }
        else                 { src = Wh;  dst = (uint2*)g_Whb;  j = i - 115712; dj = j; }
        float4 v = src[j];
        uint2 p;
        p.x = pack_bf16(v.x, v.y);
        p.y = pack_bf16(v.z, v.w);
        dst[dj] = p;
    } else {
        if (blk == 456 && threadIdx.x < 2) g_sums[threadIdx.x] = 0.0;
        if (blk == 456 && threadIdx.x == 2) g_ticket = 0u;
        int n = (blk - 456) * 256 + threadIdx.x;
        const float4* r = reinterpret_cast<const float4*>(Ef + (size_t)n * DD);
        float s = 0.0f;
#pragma unroll
        for (int i = 0; i < DD / 4; i++) {
            float4 v = r[i];
            float a = __bfloat162float(__float2bfloat16_rn(v.x));
            float b = __bfloat162float(__float2bfloat16_rn(v.y));
            float c = __bfloat162float(__float2bfloat16_rn(v.z));
            float d = __bfloat162float(__float2bfloat16_rn(v.w));
            s += a * a + b * b + c * c + d * d;
        }
        g_esq[n] = s;
    }
}

// ---------------------------------------------------------------------------
// GEMM stage (512 threads): C[128][BN] = act(A_smem[128xK] @ W[BN xK]^T + b)
// 16 warps: wm=w&3 (32m), wn=w>>2 (BN/4 n). W streamed 64-k chunks, dbl-buffered.
// ---------------------------------------------------------------------------
template <int K, int BN>
__device__ __noinline__ void gemm_stage(
    unsigned Aaddr, int ACH,
    const __nv_bfloat16* __restrict__ Wg,
    const float* __restrict__ bias,
    __nv_bfloat16* __restrict__ Ys, int NYCH, bool relu,
    unsigned wbuf)
{
    constexpr int NCH = K / 64;
    constexpr int WN  = BN / 4;        // 64 or 32
    constexpr int NP  = WN / 16;       // 4 or 2
    constexpr unsigned CHB = BN * 128u;  // bytes per W chunk buffer
    constexpr int TPR = 512 / BN;      // threads per W row
    constexpr int CPT = 8 / TPR;       // cp16 per thread per chunk

    const int tid = threadIdx.x;
    const int w = tid >> 5, L = tid & 31;
    const int wm = w & 3, wn = w >> 2;

    float acc[2][2 * NP][4];
#pragma unroll
    for (int a = 0; a < 2; a++)
#pragma unroll
        for (int b = 0; b < 2 * NP; b++)
#pragma unroll
            for (int c = 0; c < 4; c++) acc[a][b][c] = 0.0f;

    const int sn  = tid / TPR;
    const int scb = (tid % TPR) * CPT;
    const __nv_bfloat16* Wrow = Wg + (size_t)sn * K;

#pragma unroll
    for (int i = 0; i < CPT; i++) {
        int c = scb + i;
        cp16(wbuf + (sn * 8 + (c ^ (sn & 7))) * 16u, Wrow + c * 8);
    }
    cpcommit();

    for (int kc = 0; kc < NCH; kc++) {
        if (kc + 1 < NCH) {
            unsigned dstb = wbuf + ((kc + 1) & 1) * CHB;
            const __nv_bfloat16* src = Wrow + (kc + 1) * 64;
#pragma unroll
            for (int i = 0; i < CPT; i++) {
                int c = scb + i;
                cp16(dstb + (sn * 8 + (c ^ (sn & 7))) * 16u, src + c * 8);
            }
            cpcommit();
            cpwait<1>();
        } else {
            cpwait<0>();
        }
        __syncthreads();

        unsigned Bb = wbuf + (kc & 1) * CHB;
#pragma unroll
        for (int ks = 0; ks < 4; ks++) {
            unsigned a[2][4];
#pragma unroll
            for (int mt = 0; mt < 2; mt++) {
                int m  = wm * 32 + mt * 16 + (L & 15);
                int ck = kc * 8 + ks * 2 + (L >> 4);
                int sw = (ck & ~7) | ((ck & 7) ^ (m & 7));
                ldm4(Aaddr + (m * ACH + sw) * 16u, a[mt][0], a[mt][1], a[mt][2], a[mt][3]);
            }
#pragma unroll
            for (int np = 0; np < NP; np++) {
                int n   = wn * WN + np * 16 + (L & 7) + ((L >> 4) << 3);
                int ckb = ks * 2 + ((L >> 3) & 1);
                unsigned b0, b1, b2, b3;
                ldm4(Bb + (n * 8 + (ckb ^ (n & 7))) * 16u, b0, b1, b2, b3);
#pragma unroll
                for (int mt = 0; mt < 2; mt++) {
                    mma_bf16(acc[mt][np * 2 + 0], a[mt][0], a[mt][1], a[mt][2], a[mt][3], b0, b1);
                    mma_bf16(acc[mt][np * 2 + 1], a[mt][0], a[mt][1], a[mt][2], a[mt][3], b2, b3);
                }
            }
        }
        __syncthreads();
    }

    const int g = L >> 2, q2 = (L & 3) * 2;
#pragma unroll
    for (int mt = 0; mt < 2; mt++) {
#pragma unroll
        for (int nt = 0; nt < 2 * NP; nt++) {
            int ng = wn * WN + nt * 8 + q2;
            float b0 = __ldg(&bias[ng]), b1 = __ldg(&bias[ng + 1]);
            int c = ng >> 3;
#pragma unroll
            for (int h = 0; h < 2; h++) {
                int m = wm * 32 + mt * 16 + g + 8 * h;
                float v0 = acc[mt][nt][2 * h + 0] + b0;
                float v1 = acc[mt][nt][2 * h + 1] + b1;
                if (relu) { v0 = fmaxf(v0, 0.0f); v1 = fmaxf(v1, 0.0f); }
                int sw = (c & ~7) | ((c & 7) ^ (m & 7));
                *reinterpret_cast<unsigned*>(
                    reinterpret_cast<char*>(Ys) + (m * NYCH + sw) * 16 + (ng & 7) * 2)
                    = pack_bf16(v0, v1);
            }
        }
    }
}

// ---------------------------------------------------------------------------
// Megakernel (512 threads): 128 rows end-to-end + fused finalize.
// ---------------------------------------------------------------------------
__global__ __launch_bounds__(512, 1)
void mega_kernel(const float* __restrict__ action,
                 const float* __restrict__ be1, const float* __restrict__ be2,
                 const float* __restrict__ be3, const float* __restrict__ E,
                 const float* __restrict__ bd1, const float* __restrict__ bd2,
                 const float* __restrict__ bh, float* __restrict__ out) {
    extern __shared__ char sm[];
    const int tid = threadIdx.x;
    const int w = tid >> 5, L = tid & 31;
    const int wm = w & 3, wn = w >> 2;
    const int r0 = blockIdx.x * 128;

    __nv_bfloat16* sH1  = (__nv_bfloat16*)(sm + R1_OFF);
    __nv_bfloat16* sD1  = (__nv_bfloat16*)(sm + R1_OFF);
    __nv_bfloat16* sH2  = (__nv_bfloat16*)(sm + R2_OFF);
    __nv_bfloat16* sQ   = (__nv_bfloat16*)(sm + R2_OFF);
    __nv_bfloat16* sD2  = (__nv_bfloat16*)(sm + R2_OFF);
    __nv_bfloat16* sEnc = (__nv_bfloat16*)(sm + R4_OFF);
    float* sEsq    = (float*)(sm + R1_OFF);              // 8KB
    float* red_v   = (float*)(sm + R1_OFF + 8192);       // 2KB
    int*   red_i   = (int*)  (sm + R1_OFF + 10240);      // 2KB
    int*   bestidx = (int*)  (sm + R1_OFF + 12288);      // 512B

    // ---------------- Stage 1: h1 = relu(action @ We1^T + be1) ----------------
    {
        char* sActB = sm + R4_OFF;   // 128x64 bf16 swizzled (16KB)
        if (tid < 256) {
            int m = tid >> 1, hf = tid & 1;
            const float* ap = action + (size_t)(r0 + m) * AA + hf * 8;
            float4 f0 = __ldg((const float4*)ap);
            float4 f1 = __ldg((const float4*)(ap + 4));
            uint4 pk;
            pk.x = pack_bf16(f0.x, f0.y); pk.y = pack_bf16(f0.z, f0.w);
            pk.z = pack_bf16(f1.x, f1.y); pk.w = pack_bf16(f1.z, f1.w);
            *reinterpret_cast<uint4*>(sActB + (m * 8 + (hf ^ (m & 7))) * 16) = pk;
        }
        uint4 z = make_uint4(0, 0, 0, 0);
        for (int idx = tid; idx < 768; idx += 512) {
            int m = idx / 6, c = 2 + idx % 6;
            *reinterpret_cast<uint4*>(sActB + (m * 8 + (c ^ (m & 7))) * 16) = z;
        }
        __syncthreads();
        gemm_stage<64, 256>(su(sActB), 8, g_We1b, be1, sH1, 32, true, su(sm + R3_OFF));
    }
    __syncthreads();

    // ---------------- Stage 2: h2 = relu(h1 @ We2^T + be2) ----------------
    gemm_stage<256, 256>(su(sH1), 32, g_We2b, be2, sH2, 32, true, su(sm + R3_OFF));
    __syncthreads();

    // ---------------- Stage 3: enc = h2 @ We3^T + be3 ----------------
    gemm_stage<256, 128>(su(sH2), 32, g_We3b, be3, sEnc, 16, false, su(sm + R3_OFF));
    __syncthreads();

    // ---------------- Stage 4: dist + argmin over 2048 codes ----------------
    {
        unsigned ebuf  = su(sm + R3_OFF);    // 2 x 32KB E tiles
        unsigned eaddr = su(sEnc);

        cp16(su(sEsq) + tid * 16u, g_esq + tid * 4);
#pragma unroll
        for (int t = 0; t < 4; t++) {
            int idx = tid + t * 512;
            int n = idx >> 4, c = idx & 15;
            int sw = (c & 8) | ((c & 7) ^ (n & 7));
            cp16(ebuf + (n * 16 + sw) * 16u, g_Eb + (size_t)n * DD + c * 8);
        }
        cpcommit();

        float bestv[4];
        int   besti[4];
#pragma unroll
        for (int i = 0; i < 4; i++) { bestv[i] = FLT_MAX; besti[i] = 0; }

        for (int t0 = 0; t0 < 16; t0++) {
            if (t0 + 1 < 16) {
                unsigned bb = ebuf + ((t0 + 1) & 1) * 32768u;
                const __nv_bfloat16* Eg = g_Eb + (size_t)(t0 + 1) * 128 * DD;
#pragma unroll
                for (int t = 0; t < 4; t++) {
                    int idx = tid + t * 512;
                    int n = idx >> 4, c = idx & 15;
                    int sw = (c & 8) | ((c & 7) ^ (n & 7));
                    cp16(bb + (n * 16 + sw) * 16u, Eg + (size_t)n * DD + c * 8);
                }
                cpcommit();
                cpwait<1>();
            } else {
                cpwait<0>();
            }
            __syncthreads();

            unsigned Bb = ebuf + (t0 & 1) * 32768u;
            float acc[2][4][4];
#pragma unroll
            for (int a = 0; a < 2; a++)
#pragma unroll
                for (int b = 0; b < 4; b++)
#pragma unroll
                    for (int c = 0; c < 4; c++) acc[a][b][c] = 0.0f;

#pragma unroll
            for (int ks = 0; ks < 8; ks++) {
                unsigned a[2][4];
#pragma unroll
                for (int mt = 0; mt < 2; mt++) {
                    int m  = wm * 32 + mt * 16 + (L & 15);
                    int ck = ks * 2 + (L >> 4);
                    int sw = (ck & 8) | ((ck & 7) ^ (m & 7));
                    ldm4(eaddr + (m * 16 + sw) * 16u, a[mt][0], a[mt][1], a[mt][2], a[mt][3]);
                }
#pragma unroll
                for (int np = 0; np < 2; np++) {
                    int n   = wn * 32 + np * 16 + (L & 7) + ((L >> 4) << 3);
                    int ckb = ks * 2 + ((L >> 3) & 1);
                    int sw  = (ckb & 8) | ((ckb & 7) ^ (n & 7));
                    unsigned b0, b1, b2, b3;
                    ldm4(Bb + (n * 16 + sw) * 16u, b0, b1, b2, b3);
#pragma unroll
                    for (int mt = 0; mt < 2; mt++) {
                        mma_bf16(acc[mt][np * 2 + 0], a[mt][0], a[mt][1], a[mt][2], a[mt][3], b0, b1);
                        mma_bf16(acc[mt][np * 2 + 1], a[mt][0], a[mt][1], a[mt][2], a[mt][3], b2, b3);
                    }
                }
            }

            const int q2 = (L & 3) * 2;
#pragma unroll
            for (int nt = 0; nt < 4; nt++) {
                int n = t0 * 128 + wn * 32 + nt * 8 + q2;
                float es0 = sEsq[n];
                float es1 = sEsq[n + 1];
#pragma unroll
                for (int mt = 0; mt < 2; mt++) {
#pragma unroll
                    for (int h = 0; h < 2; h++) {
                        int r = mt * 2 + h;
                        float v0 = fmaf(-2.0f, acc[mt][nt][2 * h + 0], es0);
                        float v1 = fmaf(-2.0f, acc[mt][nt][2 * h + 1], es1);
                        if (v0 < bestv[r]) { bestv[r] = v0; besti[r] = n; }
                        if (v1 < bestv[r]) { bestv[r] = v1; besti[r] = n + 1; }
                    }
                }
            }
            __syncthreads();
        }

#pragma unroll
        for (int r = 0; r < 4; r++) {
            float v = bestv[r];
            int   ii = besti[r];
#pragma unroll
            for (int o = 1; o <= 2; o <<= 1) {
                float v2 = __shfl_xor_sync(0xffffffffu, v, o);
                int   i2 = __shfl_xor_sync(0xffffffffu, ii, o);
                if (v2 < v || (v2 == v && i2 < ii)) { v = v2; ii = i2; }
            }
            bestv[r] = v; besti[r] = ii;
        }
        if ((L & 3) == 0) {
            int g = L >> 2;
#pragma unroll
            for (int r = 0; r < 4; r++) {
                int mt = r >> 1, h = r & 1;
                int row = wm * 32 + mt * 16 + g + 8 * h;
                red_v[row * 4 + wn] = bestv[r];
                red_i[row * 4 + wn] = besti[r];
            }
        }
        __syncthreads();
        if (tid < 128) {
            float bv = red_v[tid * 4];
            int   bi = red_i[tid * 4];
#pragma unroll
            for (int c = 1; c < 4; c++) {
                float v = red_v[tid * 4 + c];
                int   n = red_i[tid * 4 + c];
                if (v < bv || (v == bv && n < bi)) { bv = v; bi = n; }
            }
            bestidx[tid] = bi;
        }
        __syncthreads();
    }

    // ---------------- Stage 5: gather q = E[idx], vq loss ----------------
    {
        int m = tid >> 2, qh = tid & 3;
        int code = bestidx[m];
        const float4* Ep = reinterpret_cast<const float4*>(E + ((size_t)code << 7));
        float s = 0.0f;
#pragma unroll
        for (int j = 0; j < 4; j++) {
            int c = qh * 4 + j;
            float4 q0 = __ldg(&Ep[2 * c]);
            float4 q1 = __ldg(&Ep[2 * c + 1]);
            int sw = (c & 8) | ((c & 7) ^ (m & 7));
            uint4 ev = *reinterpret_cast<uint4*>(
                reinterpret_cast<char*>(sEnc) + (m * 16 + sw) * 16);
            const __nv_bfloat162* eh = reinterpret_cast<const __nv_bfloat162*>(&ev);
            float2 e0 = __bfloat1622float2(eh[0]);
            float2 e1 = __bfloat1622float2(eh[1]);
            float2 e2 = __bfloat1622float2(eh[2]);
            float2 e3 = __bfloat1622float2(eh[3]);
            float d;
            d = e0.x - q0.x; s += d * d;  d = e0.y - q0.y; s += d * d;
            d = e1.x - q0.z; s += d * d;  d = e1.y - q0.w; s += d * d;
            d = e2.x - q1.x; s += d * d;  d = e2.y - q1.y; s += d * d;
            d = e3.x - q1.z; s += d * d;  d = e3.y - q1.w; s += d * d;
            uint4 pk;
            pk.x = pack_bf16(q0.x, q0.y); pk.y = pack_bf16(q0.z, q0.w);
            pk.z = pack_bf16(q1.x, q1.y); pk.w = pack_bf16(q1.z, q1.w);
            *reinterpret_cast<uint4*>(
                reinterpret_cast<char*>(sQ) + (m * 16 + sw) * 16) = pk;
        }
        block_reduce_add_to(s, &g_sums[0]);
    }
    __syncthreads();

    // ---------------- Stage 6/7: decoder ----------------
    gemm_stage<128, 256>(su(sQ), 16, g_Wd1b, bd1, sD1, 32, true, su(sm + R3_OFF));
    __syncthreads();
    gemm_stage<256, 256>(su(sD1), 32, g_Wd2b, bd2, sD2, 32, true, su(sm + R3_OFF));
    __syncthreads();

    // ---------------- Stage 8: head mma + tanh + recons loss ----------------
    {
        unsigned whaddr = su(sm + R3_OFF);   // 16x256 bf16 swizzled (8KB)
        {
            int n = tid >> 5, c = tid & 31;
            int sw = (c & 24) | ((c & 7) ^ (n & 7));
            cp16(whaddr + (n * 32 + sw) * 16u, g_Whb + (size_t)n * HH + c * 8);
        }
        cpcommit(); cpwait<0>();
        __syncthreads();

        float s = 0.0f;
        if (w < 8) {
            unsigned daddr = su(sD2);
            float acc[2][4];
#pragma unroll
            for (int a = 0; a < 2; a++)
#pragma unroll
                for (int c = 0; c < 4; c++) acc[a][c] = 0.0f;

#pragma unroll
            for (int ks = 0; ks < 16; ks++) {
                int m  = w * 16 + (L & 15);
                int ck = ks * 2 + (L >> 4);
                int sw = (ck & 24) | ((ck & 7) ^ (m & 7));
                unsigned a0, a1, a2, a3;
                ldm4(daddr + (m * 32 + sw) * 16u, a0, a1, a2, a3);
                int n   = (L & 7) + ((L >> 4) << 3);
                int ckb = ks * 2 + ((L >> 3) & 1);
                int swb = (ckb & 24) | ((ckb & 7) ^ (n & 7));
                unsigned b0, b1, b2, b3;
                ldm4(whaddr + (n * 32 + swb) * 16u, b0, b1, b2, b3);
                mma_bf16(acc[0], a0, a1, a2, a3, b0, b1);
                mma_bf16(acc[1], a0, a1, a2, a3, b2, b3);
            }

            const int g = L >> 2, q2 = (L & 3) * 2;
#pragma unroll
            for (int nt = 0; nt < 2; nt++) {
                int n = nt * 8 + q2;
                float b0 = __ldg(&bh[n]), b1 = __ldg(&bh[n + 1]);
#pragma unroll
                for (int h = 0; h < 2; h++) {
                    int m = w * 16 + g + 8 * h;
                    const float* ar = action + (size_t)(r0 + m) * AA + n;
                    float t0 = tanhf(acc[nt][2 * h + 0] + b0) - __ldg(&ar[0]);
                    float t1 = tanhf(acc[nt][2 * h + 1] + b1) - __ldg(&ar[1]);
                    s += t0 * t0 + t1 * t1;
                }
            }
        }
        block_reduce_add_to(s, &g_sums[1]);
    }

    // ---------------- Fused finalize: last block writes the scalar ----------
    if (tid == 0) {
        __threadfence();
        unsigned t = atomicAdd(&g_ticket, 1u);
        if (t == gridDim.x - 1) {
            double vq  = g_sums[0] / ((double)BB * (double)DD);
            double rec = g_sums[1] / ((double)BB * (double)AA);
            out[0] = (float)(rec + 1.25 * vq);
        }
    }
}

// ---------------------------------------------------------------------------
// Launch
// ---------------------------------------------------------------------------
extern "C" void kernel_launch(void* const* d_in, const int* in_sizes, int n_in,
                              void* d_out, int out_size) {
    const float* action = (const float*)d_in[0];
    const float* We1    = (const float*)d_in[1];
    const float* be1    = (const float*)d_in[2];
    const float* We2    = (const float*)d_in[3];
    const float* be2    = (const float*)d_in[4];
    const float* We3    = (const float*)d_in[5];
    const float* be3    = (const float*)d_in[6];
    const float* E      = (const float*)d_in[7];
    const float* Wd1    = (const float*)d_in[8];
    const float* bd1    = (const float*)d_in[9];
    const float* Wd2    = (const float*)d_in[10];
    const float* bd2    = (const float*)d_in[11];
    const float* Wh     = (const float*)d_in[12];
    const float* bh     = (const float*)d_in[13];
    float* out = (float*)d_out;

    cudaFuncSetAttribute((const void*)mega_kernel,
                         cudaFuncAttributeMaxDynamicSharedMemorySize, SMEM_TOTAL);

    prep_kernel<<<464, 256>>>((const float4*)We1, (const float4*)We2,
                              (const float4*)We3, (const float4*)Wd1,
                              (const float4*)Wd2, (const float4*)Wh,
                              (const float4*)E, E);
    mega_kernel<<<BB / 128, 512, SMEM_TOTAL>>>(action, be1, be2, be3, E,
                                               bd1, bd2, bh, out);
}